// round 7
// baseline (speedup 1.0000x reference)
#include <cuda_runtime.h>
#include <cuda_bf16.h>
#include <cstddef>

// Problem shapes (fixed by setup_inputs): F=2, B=64, S=512, D=768
#define Fdim  2
#define Bdim  64
#define FB    (Fdim * Bdim)      // 128
#define Sdim  512
#define Ddim  768
#define D4    (Ddim / 4)         // 192 float4 per row
#define SPLIT 8                  // S-splits per (f,b)
#define RPB   (Sdim / SPLIT)     // 64 rows per block
#define NBLK  (FB * SPLIT)       // 1024 blocks

#define EPSV  1e-9f

// Deterministic scratch (no device-side allocation allowed)
__device__ float g_partial[NBLK];
__device__ int   g_count = 0;      // last-block-done counter (self-resetting)

// ---------------------------------------------------------------------------
// Fused kernel, branch-free inner loop with 8-deep load batching:
//  - compaction: ballot+popc builds the list of mask=1 rows in smem
//  - main loop: 8 UNCONDITIONAL streaming loads in flight per iteration
//  phase 2 (last block): T_fb = fixed-order sum of partials;
//                        out = (1/F) * sum_fb T/(T+eps)
// 192 threads == D4 lanes; each thread owns one float4 column slice.
// ---------------------------------------------------------------------------
__global__ __launch_bounds__(192, 6)
void noun_fused_kernel(const float4* __restrict__ tok,
                       const float4* __restrict__ sent,
                       const int*    __restrict__ mask,
                       float*        __restrict__ out)
{
    const int fb  = blockIdx.x >> 3;        // / SPLIT
    const int sp  = blockIdx.x & (SPLIT - 1);
    const int tid = threadIdx.x;            // 0..191

    __shared__ float4        s_sent[D4];
    __shared__ unsigned      s_ballot[2];
    __shared__ unsigned char s_rows[RPB];
    __shared__ int           s_cnt;

    s_sent[tid] = sent[(size_t)fb * D4 + tid];

    // --- Compaction: rows 0..63 handled by warps 0,1 (full-warp ballots) ---
    const int w = tid >> 5, l = tid & 31;
    if (tid < RPB) {
        int m = mask[fb * Sdim + sp * RPB + tid];
        unsigned bal = __ballot_sync(0xffffffffu, m != 0);
        if (l == 0) s_ballot[w] = bal;
    }
    __syncthreads();

    if (tid < RPB) {
        unsigned bal = s_ballot[w];
        if ((bal >> l) & 1u) {
            int pos = __popc(bal & ((1u << l) - 1u))
                    + (w ? __popc(s_ballot[0]) : 0);
            s_rows[pos] = (unsigned char)tid;
        }
        if (tid == 0)
            s_cnt = __popc(s_ballot[0]) + __popc(s_ballot[1]);
    }
    __syncthreads();

    const float4 w4 = s_sent[tid];          // register-resident weight slice
    const float4* base = tok + ((size_t)fb * Sdim + (size_t)sp * RPB) * D4 + tid;
    const int cnt = s_cnt;

    // --- Branch-free main loop: 8 streaming loads in flight ---
    float a0 = 0.f, a1 = 0.f, a2 = 0.f, a3 = 0.f;
    float a4 = 0.f, a5 = 0.f, a6 = 0.f, a7 = 0.f;
    int r = 0;
    for (; r + 8 <= cnt; r += 8) {
        const int i0 = s_rows[r + 0], i1 = s_rows[r + 1];
        const int i2 = s_rows[r + 2], i3 = s_rows[r + 3];
        const int i4 = s_rows[r + 4], i5 = s_rows[r + 5];
        const int i6 = s_rows[r + 6], i7 = s_rows[r + 7];
        float4 t0 = __ldcs(base + (size_t)i0 * D4);
        float4 t1 = __ldcs(base + (size_t)i1 * D4);
        float4 t2 = __ldcs(base + (size_t)i2 * D4);
        float4 t3 = __ldcs(base + (size_t)i3 * D4);
        float4 t4 = __ldcs(base + (size_t)i4 * D4);
        float4 t5 = __ldcs(base + (size_t)i5 * D4);
        float4 t6 = __ldcs(base + (size_t)i6 * D4);
        float4 t7 = __ldcs(base + (size_t)i7 * D4);
        a0 = fmaf(t0.x, w4.x, a0); a0 = fmaf(t0.y, w4.y, a0);
        a0 = fmaf(t0.z, w4.z, a0); a0 = fmaf(t0.w, w4.w, a0);
        a1 = fmaf(t1.x, w4.x, a1); a1 = fmaf(t1.y, w4.y, a1);
        a1 = fmaf(t1.z, w4.z, a1); a1 = fmaf(t1.w, w4.w, a1);
        a2 = fmaf(t2.x, w4.x, a2); a2 = fmaf(t2.y, w4.y, a2);
        a2 = fmaf(t2.z, w4.z, a2); a2 = fmaf(t2.w, w4.w, a2);
        a3 = fmaf(t3.x, w4.x, a3); a3 = fmaf(t3.y, w4.y, a3);
        a3 = fmaf(t3.z, w4.z, a3); a3 = fmaf(t3.w, w4.w, a3);
        a4 = fmaf(t4.x, w4.x, a4); a4 = fmaf(t4.y, w4.y, a4);
        a4 = fmaf(t4.z, w4.z, a4); a4 = fmaf(t4.w, w4.w, a4);
        a5 = fmaf(t5.x, w4.x, a5); a5 = fmaf(t5.y, w4.y, a5);
        a5 = fmaf(t5.z, w4.z, a5); a5 = fmaf(t5.w, w4.w, a5);
        a6 = fmaf(t6.x, w4.x, a6); a6 = fmaf(t6.y, w4.y, a6);
        a6 = fmaf(t6.z, w4.z, a6); a6 = fmaf(t6.w, w4.w, a6);
        a7 = fmaf(t7.x, w4.x, a7); a7 = fmaf(t7.y, w4.y, a7);
        a7 = fmaf(t7.z, w4.z, a7); a7 = fmaf(t7.w, w4.w, a7);
    }
    if (r + 4 <= cnt) {                     // 4-wide tail batch
        const int i0 = s_rows[r + 0], i1 = s_rows[r + 1];
        const int i2 = s_rows[r + 2], i3 = s_rows[r + 3];
        float4 t0 = __ldcs(base + (size_t)i0 * D4);
        float4 t1 = __ldcs(base + (size_t)i1 * D4);
        float4 t2 = __ldcs(base + (size_t)i2 * D4);
        float4 t3 = __ldcs(base + (size_t)i3 * D4);
        a0 = fmaf(t0.x, w4.x, a0); a0 = fmaf(t0.y, w4.y, a0);
        a0 = fmaf(t0.z, w4.z, a0); a0 = fmaf(t0.w, w4.w, a0);
        a1 = fmaf(t1.x, w4.x, a1); a1 = fmaf(t1.y, w4.y, a1);
        a1 = fmaf(t1.z, w4.z, a1); a1 = fmaf(t1.w, w4.w, a1);
        a2 = fmaf(t2.x, w4.x, a2); a2 = fmaf(t2.y, w4.y, a2);
        a2 = fmaf(t2.z, w4.z, a2); a2 = fmaf(t2.w, w4.w, a2);
        a3 = fmaf(t3.x, w4.x, a3); a3 = fmaf(t3.y, w4.y, a3);
        a3 = fmaf(t3.z, w4.z, a3); a3 = fmaf(t3.w, w4.w, a3);
        r += 4;
    }
    for (; r < cnt; ++r) {                  // <=3 remainder rows
        float4 t = __ldcs(base + (size_t)s_rows[r] * D4);
        a0 = fmaf(t.x, w4.x, a0); a0 = fmaf(t.y, w4.y, a0);
        a0 = fmaf(t.z, w4.z, a0); a0 = fmaf(t.w, w4.w, a0);
    }
    float acc = ((a0 + a1) + (a2 + a3)) + ((a4 + a5) + (a6 + a7));

    // --- Block reduction: 6 warps ---
    #pragma unroll
    for (int o = 16; o > 0; o >>= 1)
        acc += __shfl_xor_sync(0xffffffffu, acc, o);

    __shared__ float s_warp[6];
    __shared__ int   s_islast;
    if (l == 0)
        s_warp[w] = acc;
    __syncthreads();

    if (tid == 0) {
        float s = 0.0f;
        #pragma unroll
        for (int i = 0; i < 6; i++) s += s_warp[i];
        g_partial[blockIdx.x] = s;          // deterministic (no atomics on data)
        __threadfence();                    // publish partial before counting
        int prev = atomicAdd(&g_count, 1);
        s_islast = (prev == NBLK - 1);
    }
    __syncthreads();

    if (!s_islast) return;

    // ---- Phase 2: last block computes the final scalar (L2-hot reads) ----
    __threadfence();                        // acquire: see all partials

    float c = 0.0f;
    if (tid < FB) {                         // 128 active lanes = warps 0..3
        float t = 0.0f;
        #pragma unroll
        for (int i = 0; i < SPLIT; i++)     // fixed order -> deterministic
            t += g_partial[tid * SPLIT + i];
        c = t / (t + EPSV);
    }

    #pragma unroll
    for (int o = 16; o > 0; o >>= 1)
        c += __shfl_xor_sync(0xffffffffu, c, o);

    if (l == 0)
        s_warp[w] = c;
    __syncthreads();

    if (tid == 0) {
        out[0] = (s_warp[0] + s_warp[1] + s_warp[2] + s_warp[3]) / (float)Fdim;
        g_count = 0;                        // reset for next graph replay
    }
}

// ---------------------------------------------------------------------------
// Entry point. Inputs (metadata order):
//   d_in[0] token_embeddings   f32 [F,B,S,D]
//   d_in[1] sentence_embedding f32 [F,B,D]
//   d_in[2] attention_mask     i32 [F,B,S]
// d_out: 1 float scalar
// ---------------------------------------------------------------------------
extern "C" void kernel_launch(void* const* d_in, const int* in_sizes, int n_in,
                              void* d_out, int out_size)
{
    (void)in_sizes; (void)n_in; (void)out_size;
    const float4* tok  = (const float4*)d_in[0];
    const float4* sent = (const float4*)d_in[1];
    const int*    mask = (const int*)d_in[2];
    float*        out  = (float*)d_out;

    noun_fused_kernel<<<NBLK, 192>>>(tok, sent, mask, out);
}